// round 6
// baseline (speedup 1.0000x reference)
#include <cuda_runtime.h>

// out[m][n] = C[m][n] * D[n];  8192 x 8192 f32, row-major.
// Persistent single-wave grid: 888 blocks = 148 SMs x 6 resident blocks
// (regs=32 -> occ limit 6 with __launch_bounds__(256,6)). Grid-stride loop,
// 4 front-batched float4 loads per iteration (MLP=4), spaced STRIDE apart.
// STRIDE = 888*256 = 227,328 = 111 * 2048  -> multiple of NR4, so every
// thread's column index (and D scale) is invariant across ALL iterations:
// D is loaded exactly once per thread.

static constexpr int       NR4    = 2048;                       // float4s per row
static constexpr int       STRIDE = 888 * 256;                  // 227,328
static constexpr long long TOTAL4 = 16777216LL;                 // 8192*2048 float4s

__global__ __launch_bounds__(256, 6)
void colscale_kernel(const float4* __restrict__ C,
                     const float4* __restrict__ D,
                     float4* __restrict__ out)
{
    const int tid0 = blockIdx.x * 256 + threadIdx.x;   // 0 .. 227,327

    // STRIDE % NR4 == 0 -> same column for every element this thread touches.
    const float4 d = __ldg(&D[tid0 & (NR4 - 1)]);

    long long i = tid0;

    // Main loop: 4 front-batched loads, then 4 stores. 16,777,216 / 227,328
    // = 73.8 elements/thread -> 18 full batches of 4 plus a short tail.
    for (; i + 3LL * STRIDE < TOTAL4; i += 4LL * STRIDE) {
        const long long i0 = i;
        const long long i1 = i +      STRIDE;
        const long long i2 = i + 2LL * STRIDE;
        const long long i3 = i + 3LL * STRIDE;

        float4 c0 = C[i0];
        float4 c1 = C[i1];
        float4 c2 = C[i2];
        float4 c3 = C[i3];

        c0.x *= d.x; c0.y *= d.y; c0.z *= d.z; c0.w *= d.w;
        c1.x *= d.x; c1.y *= d.y; c1.z *= d.z; c1.w *= d.w;
        c2.x *= d.x; c2.y *= d.y; c2.z *= d.z; c2.w *= d.w;
        c3.x *= d.x; c3.y *= d.y; c3.z *= d.z; c3.w *= d.w;

        out[i0] = c0;
        out[i1] = c1;
        out[i2] = c2;
        out[i3] = c3;
    }

    // Tail: remaining 0..3 elements for this thread.
    for (; i < TOTAL4; i += STRIDE) {
        float4 c = C[i];
        c.x *= d.x; c.y *= d.y; c.z *= d.z; c.w *= d.w;
        out[i] = c;
    }
}

extern "C" void kernel_launch(void* const* d_in, const int* in_sizes, int n_in,
                              void* d_out, int out_size)
{
    const float4* C = (const float4*)d_in[0];
    const float4* D = (const float4*)d_in[1];
    float4* out     = (float4*)d_out;

    colscale_kernel<<<888, 256>>>(C, D, out);
}

// round 8
// speedup vs baseline: 1.1468x; 1.1468x over previous
#include <cuda_runtime.h>

// out[m][n] = C[m][n] * D[n];  8192 x 8192 f32, row-major.
// R3 structure with Blackwell 256-bit vector accesses (ld/st.global.v8.f32):
// 8192 blocks x 256 threads x 4 float8 = 8,388,608 float8s (full matrix).
// STRIDE = 8192*256 = 2,097,152 float8s (64 MB apart), multiple of NR8=1024,
// so each thread's column (and D scale) is invariant -> D loaded once.

static constexpr int NR8    = 1024;          // float8s per row
static constexpr int STRIDE = 8192 * 256;    // 2,097,152 float8s

struct f8 { float v[8]; };

__device__ __forceinline__ f8 ldg_v8(const float* p) {
    f8 r;
    asm volatile("ld.global.v8.f32 {%0,%1,%2,%3,%4,%5,%6,%7}, [%8];"
                 : "=f"(r.v[0]), "=f"(r.v[1]), "=f"(r.v[2]), "=f"(r.v[3]),
                   "=f"(r.v[4]), "=f"(r.v[5]), "=f"(r.v[6]), "=f"(r.v[7])
                 : "l"(p));
    return r;
}

__device__ __forceinline__ void stg_v8(float* p, const f8& r) {
    asm volatile("st.global.v8.f32 [%0], {%1,%2,%3,%4,%5,%6,%7,%8};"
                 :: "l"(p),
                    "f"(r.v[0]), "f"(r.v[1]), "f"(r.v[2]), "f"(r.v[3]),
                    "f"(r.v[4]), "f"(r.v[5]), "f"(r.v[6]), "f"(r.v[7])
                 : "memory");
}

__global__ __launch_bounds__(256)
void colscale_kernel(const float* __restrict__ C,
                     const float* __restrict__ D,
                     float* __restrict__ out)
{
    const int i = blockIdx.x * 256 + threadIdx.x;   // 0 .. 2,097,151 (float8 idx)

    // Column is invariant across all 4 batches (STRIDE % NR8 == 0).
    const f8 d = ldg_v8(&D[(i & (NR8 - 1)) * 8]);

    const long long b0 = (long long)i * 8;
    const long long b1 = (long long)(i + STRIDE) * 8;
    const long long b2 = (long long)(i + 2 * STRIDE) * 8;
    const long long b3 = (long long)(i + 3 * STRIDE) * 8;

    // Front-batched 256-bit loads (MLP=4), 64 MB apart.
    f8 c0 = ldg_v8(C + b0);
    f8 c1 = ldg_v8(C + b1);
    f8 c2 = ldg_v8(C + b2);
    f8 c3 = ldg_v8(C + b3);

    #pragma unroll
    for (int k = 0; k < 8; k++) {
        c0.v[k] *= d.v[k];
        c1.v[k] *= d.v[k];
        c2.v[k] *= d.v[k];
        c3.v[k] *= d.v[k];
    }

    stg_v8(out + b0, c0);
    stg_v8(out + b1, c1);
    stg_v8(out + b2, c2);
    stg_v8(out + b3, c3);
}

extern "C" void kernel_launch(void* const* d_in, const int* in_sizes, int n_in,
                              void* d_out, int out_size)
{
    const float* C = (const float*)d_in[0];
    const float* D = (const float*)d_in[1];
    float* out     = (float*)d_out;

    colscale_kernel<<<8192, 256>>>(C, D, out);
}